// round 1
// baseline (speedup 1.0000x reference)
#include <cuda_runtime.h>
#include <math.h>
#include <stdint.h>

#define T_DIM 4096
#define D_DIM 1024
#define H_DIM 1024
#define B_MAX 8

#define CHUNKS 32
#define CLEN   (T_DIM / CHUNKS)   // 128

// ---------------- scratch (device globals: no allocations allowed) ----------
__device__ float g_logf[(size_t)B_MAX * T_DIM * H_DIM];   // 134 MB
__device__ float g_logv[(size_t)B_MAX * T_DIM * H_DIM];   // 134 MB
__device__ float g_cA[(size_t)B_MAX * CHUNKS * H_DIM];
__device__ float g_cB[(size_t)B_MAX * CHUNKS * H_DIM];
__device__ float g_cS[(size_t)B_MAX * CHUNKS * H_DIM];

// ---------------- math helpers ----------------------------------------------
__device__ __forceinline__ float splus(float x) {
    // stable softplus: log(1+exp(x))
    return fmaxf(x, 0.0f) + log1pf(expf(-fabsf(x)));
}
__device__ __forceinline__ float lae(float a, float b) {
    // logaddexp, both finite in our use
    float m = fmaxf(a, b);
    float d = fabsf(a - b);
    return m + log1pf(expf(-d));
}
__device__ __forceinline__ float log_g(float x) {
    return (x >= 0.0f) ? logf(x + 0.5f) : -splus(-x);
}

// ---------------- fused 3-gate GEMM + epilogue -------------------------------
// z_g[m][h] = sum_d x[m][d] * W_g[h][d] + b_g[h]; then gate math -> g_logf/g_logv
#define BM 128
#define BN 64
#define BK 16
#define TM 8
#define TN 4
// 256 threads: 16 (m-groups) x 16 (n-groups)

__global__ void __launch_bounds__(256)
gemm_epi(const float* __restrict__ x,
         const float* __restrict__ Wf, const float* __restrict__ bf,
         const float* __restrict__ Wi, const float* __restrict__ bi,
         const float* __restrict__ Wh, const float* __restrict__ bh,
         int M)
{
    __shared__ __align__(16) float xs[2][BK][BM + 4];
    __shared__ __align__(16) float ws[2][3][BK][BN + 4];

    const int tid = threadIdx.x;
    const int m0 = blockIdx.y * BM;
    const int n0 = blockIdx.x * BN;

    const int tmBase = (tid / 16) * TM;   // 0..120 step 8
    const int tnBase = (tid % 16) * TN;   // 0..60  step 4

    // ---- loader index precompute ----
    // x: 512 float4 per tile, 2 per thread
    const int xr0 = (tid) >> 2;           // row for p=0  (0..63)
    const int xq0 = (tid) & 3;            // float4-in-row
    const int xr1 = (tid + 256) >> 2;     // row for p=1  (64..127)
    const int xq1 = (tid + 256) & 3;
    // W: per gate 256 float4, 1 per thread per gate
    const int wr = tid >> 2;              // 0..63
    const int wq = tid & 3;

    const float* Wg[3] = {Wf, Wi, Wh};

    float acc[3][TM][TN];
#pragma unroll
    for (int g = 0; g < 3; g++)
#pragma unroll
        for (int i = 0; i < TM; i++)
#pragma unroll
            for (int j = 0; j < TN; j++) acc[g][i][j] = 0.0f;

    const int NT = D_DIM / BK;   // 64 k-tiles

    float4 xv0, xv1, wv0, wv1, wv2;

    // prologue: load tile 0
    {
        const int k0 = 0;
        xv0 = *(const float4*)&x[(size_t)(m0 + xr0) * D_DIM + k0 + xq0 * 4];
        xv1 = *(const float4*)&x[(size_t)(m0 + xr1) * D_DIM + k0 + xq1 * 4];
        wv0 = *(const float4*)&Wg[0][(size_t)(n0 + wr) * D_DIM + k0 + wq * 4];
        wv1 = *(const float4*)&Wg[1][(size_t)(n0 + wr) * D_DIM + k0 + wq * 4];
        wv2 = *(const float4*)&Wg[2][(size_t)(n0 + wr) * D_DIM + k0 + wq * 4];
        // store to buffer 0 (transposed: smem[k][row])
        xs[0][xq0 * 4 + 0][xr0] = xv0.x; xs[0][xq0 * 4 + 1][xr0] = xv0.y;
        xs[0][xq0 * 4 + 2][xr0] = xv0.z; xs[0][xq0 * 4 + 3][xr0] = xv0.w;
        xs[0][xq1 * 4 + 0][xr1] = xv1.x; xs[0][xq1 * 4 + 1][xr1] = xv1.y;
        xs[0][xq1 * 4 + 2][xr1] = xv1.z; xs[0][xq1 * 4 + 3][xr1] = xv1.w;
        ws[0][0][wq * 4 + 0][wr] = wv0.x; ws[0][0][wq * 4 + 1][wr] = wv0.y;
        ws[0][0][wq * 4 + 2][wr] = wv0.z; ws[0][0][wq * 4 + 3][wr] = wv0.w;
        ws[0][1][wq * 4 + 0][wr] = wv1.x; ws[0][1][wq * 4 + 1][wr] = wv1.y;
        ws[0][1][wq * 4 + 2][wr] = wv1.z; ws[0][1][wq * 4 + 3][wr] = wv1.w;
        ws[0][2][wq * 4 + 0][wr] = wv2.x; ws[0][2][wq * 4 + 1][wr] = wv2.y;
        ws[0][2][wq * 4 + 2][wr] = wv2.z; ws[0][2][wq * 4 + 3][wr] = wv2.w;
    }
    __syncthreads();

    for (int kt = 0; kt < NT; kt++) {
        const int buf = kt & 1;
        const int nbuf = buf ^ 1;
        // prefetch next tile (global -> regs)
        if (kt + 1 < NT) {
            const int k0 = (kt + 1) * BK;
            xv0 = *(const float4*)&x[(size_t)(m0 + xr0) * D_DIM + k0 + xq0 * 4];
            xv1 = *(const float4*)&x[(size_t)(m0 + xr1) * D_DIM + k0 + xq1 * 4];
            wv0 = *(const float4*)&Wg[0][(size_t)(n0 + wr) * D_DIM + k0 + wq * 4];
            wv1 = *(const float4*)&Wg[1][(size_t)(n0 + wr) * D_DIM + k0 + wq * 4];
            wv2 = *(const float4*)&Wg[2][(size_t)(n0 + wr) * D_DIM + k0 + wq * 4];
        }

        // compute on current buffer
#pragma unroll
        for (int k = 0; k < BK; k++) {
            float4 a0 = *(const float4*)&xs[buf][k][tmBase];
            float4 a1 = *(const float4*)&xs[buf][k][tmBase + 4];
            float xr[8] = {a0.x, a0.y, a0.z, a0.w, a1.x, a1.y, a1.z, a1.w};
#pragma unroll
            for (int g = 0; g < 3; g++) {
                float4 w4 = *(const float4*)&ws[buf][g][k][tnBase];
                float wrv[4] = {w4.x, w4.y, w4.z, w4.w};
#pragma unroll
                for (int i = 0; i < TM; i++)
#pragma unroll
                    for (int j = 0; j < TN; j++)
                        acc[g][i][j] = fmaf(xr[i], wrv[j], acc[g][i][j]);
            }
        }

        // store prefetched tile into the other buffer
        if (kt + 1 < NT) {
            xs[nbuf][xq0 * 4 + 0][xr0] = xv0.x; xs[nbuf][xq0 * 4 + 1][xr0] = xv0.y;
            xs[nbuf][xq0 * 4 + 2][xr0] = xv0.z; xs[nbuf][xq0 * 4 + 3][xr0] = xv0.w;
            xs[nbuf][xq1 * 4 + 0][xr1] = xv1.x; xs[nbuf][xq1 * 4 + 1][xr1] = xv1.y;
            xs[nbuf][xq1 * 4 + 2][xr1] = xv1.z; xs[nbuf][xq1 * 4 + 3][xr1] = xv1.w;
            ws[nbuf][0][wq * 4 + 0][wr] = wv0.x; ws[nbuf][0][wq * 4 + 1][wr] = wv0.y;
            ws[nbuf][0][wq * 4 + 2][wr] = wv0.z; ws[nbuf][0][wq * 4 + 3][wr] = wv0.w;
            ws[nbuf][1][wq * 4 + 0][wr] = wv1.x; ws[nbuf][1][wq * 4 + 1][wr] = wv1.y;
            ws[nbuf][1][wq * 4 + 2][wr] = wv1.z; ws[nbuf][1][wq * 4 + 3][wr] = wv1.w;
            ws[nbuf][2][wq * 4 + 0][wr] = wv2.x; ws[nbuf][2][wq * 4 + 1][wr] = wv2.y;
            ws[nbuf][2][wq * 4 + 2][wr] = wv2.z; ws[nbuf][2][wq * 4 + 3][wr] = wv2.w;
        }
        __syncthreads();
    }

    // ---- epilogue: bias + gate math -> g_logf / g_logv ----
    float bfv[TN], biv[TN], bhv[TN];
#pragma unroll
    for (int j = 0; j < TN; j++) {
        bfv[j] = bf[n0 + tnBase + j];
        biv[j] = bi[n0 + tnBase + j];
        bhv[j] = bh[n0 + tnBase + j];
    }

#pragma unroll
    for (int i = 0; i < TM; i++) {
        const int m = m0 + tmBase + i;
        const size_t rowoff = (size_t)m * H_DIM + n0 + tnBase;
#pragma unroll
        for (int j = 0; j < TN; j++) {
            float zf = acc[0][i][j] + bfv[j];
            float zi = acc[1][i][j] + biv[j];
            float zh = acc[2][i][j] + bhv[j];
            float diff  = splus(-zf) - splus(-zi);
            float logF  = -splus(diff);
            float logI  = -splus(-diff);
            float logGh = log_g(zh);
            g_logf[rowoff + j] = logF;
            g_logv[rowoff + j] = logI + logGh;
        }
    }
}

// ---------------- pass 1: per-chunk composed operator ------------------------
__global__ void scan_chunks(int B)
{
    const size_t gid = (size_t)blockIdx.x * blockDim.x + threadIdx.x;
    const int h = (int)(gid % H_DIM);
    const size_t bc = gid / H_DIM;
    const int c = (int)(bc % CHUNKS);
    const int b = (int)(bc / CHUNKS);
    if (b >= B) return;

    size_t idx = ((size_t)b * T_DIM + (size_t)c * CLEN) * H_DIM + h;
    float A  = g_logf[idx];
    float Bv = g_logv[idx];
#pragma unroll 4
    for (int t = 1; t < CLEN; t++) {
        idx += H_DIM;
        float a  = g_logf[idx];
        float bb = g_logv[idx];
        A += a;
        Bv = lae(Bv + a, bb);
    }
    const size_t co = ((size_t)b * CHUNKS + c) * H_DIM + h;
    g_cA[co] = A;
    g_cB[co] = Bv;
}

// ---------------- pass 2: scan across chunks (per channel) -------------------
__global__ void scan_across(const float* __restrict__ h0, int B)
{
    const size_t gid = (size_t)blockIdx.x * blockDim.x + threadIdx.x;
    const int h = (int)(gid % H_DIM);
    const int b = (int)(gid / H_DIM);
    if (b >= B) return;

    float state = log_g(h0[(size_t)b * H_DIM + h]);
#pragma unroll
    for (int c = 0; c < CHUNKS; c++) {
        const size_t co = ((size_t)b * CHUNKS + c) * H_DIM + h;
        g_cS[co] = state;                       // state entering chunk c
        state = lae(state + g_cA[co], g_cB[co]);
    }
}

// ---------------- pass 3: final within-chunk scan + exp ----------------------
__global__ void scan_final(float* __restrict__ out, int B)
{
    const size_t gid = (size_t)blockIdx.x * blockDim.x + threadIdx.x;
    const int h = (int)(gid % H_DIM);
    const size_t bc = gid / H_DIM;
    const int c = (int)(bc % CHUNKS);
    const int b = (int)(bc / CHUNKS);
    if (b >= B) return;

    const size_t co = ((size_t)b * CHUNKS + c) * H_DIM + h;
    float state = g_cS[co];

    size_t idx = ((size_t)b * T_DIM + (size_t)c * CLEN) * H_DIM + h;
#pragma unroll 4
    for (int t = 0; t < CLEN; t++) {
        float a  = g_logf[idx];
        float bb = g_logv[idx];
        state = lae(state + a, bb);
        out[idx] = expf(state);
        idx += H_DIM;
    }
}

// ---------------- launch ------------------------------------------------------
extern "C" void kernel_launch(void* const* d_in, const int* in_sizes, int n_in,
                              void* d_out, int out_size)
{
    const float* x  = (const float*)d_in[0];
    const float* h0 = (const float*)d_in[1];
    const float* Wf = (const float*)d_in[2];
    const float* bf = (const float*)d_in[3];
    const float* Wi = (const float*)d_in[4];
    const float* bi = (const float*)d_in[5];
    const float* Wh = (const float*)d_in[6];
    const float* bh = (const float*)d_in[7];
    float* out = (float*)d_out;

    const int M = in_sizes[0] / D_DIM;   // B*T = 32768
    const int B = M / T_DIM;             // 8

    dim3 gGemm(H_DIM / BN, M / BM);      // (16, 256)
    gemm_epi<<<gGemm, 256>>>(x, Wf, bf, Wi, bi, Wh, bh, M);

    const int nChunkThreads = B * CHUNKS * H_DIM;     // 262144
    scan_chunks<<<nChunkThreads / 256, 256>>>(B);

    const int nChanThreads = B * H_DIM;               // 8192
    scan_across<<<nChanThreads / 256, 256>>>(h0, B);

    scan_final<<<nChunkThreads / 256, 256>>>(out, B);
}

// round 2
// speedup vs baseline: 2.4507x; 2.4507x over previous
#include <cuda_runtime.h>
#include <math.h>
#include <stdint.h>

#define T_DIM 4096
#define D_DIM 1024
#define H_DIM 1024
#define B_MAX 8

#define CHUNKS 32
#define CLEN   (T_DIM / CHUNKS)   // 128

// ---------------- scratch (device globals: no allocations allowed) ----------
__device__ float g_logf[(size_t)B_MAX * T_DIM * H_DIM];   // 134 MB
__device__ float g_logv[(size_t)B_MAX * T_DIM * H_DIM];   // 134 MB
__device__ float g_cA[(size_t)B_MAX * CHUNKS * H_DIM];
__device__ float g_cB[(size_t)B_MAX * CHUNKS * H_DIM];
__device__ float g_cS[(size_t)B_MAX * CHUNKS * H_DIM];

// ---------------- math helpers ----------------------------------------------
__device__ __forceinline__ float splus(float x) {
    return fmaxf(x, 0.0f) + log1pf(expf(-fabsf(x)));
}
__device__ __forceinline__ float lae(float a, float b) {
    float m = fmaxf(a, b);
    float d = fabsf(a - b);
    return m + log1pf(expf(-d));
}
__device__ __forceinline__ float log_g(float x) {
    return (x >= 0.0f) ? logf(x + 0.5f) : -splus(-x);
}
__device__ __forceinline__ uint32_t f2tf32(float f) {
    uint32_t r;
    asm("cvt.rna.tf32.f32 %0, %1;" : "=r"(r) : "f"(f));
    return r;
}

// ---------------- tensor-core fused 3-gate GEMM + epilogue -------------------
// z_g[m][h] = sum_d x[m][d] * W_g[h][d] + b_g[h]   (tf32 mma.m16n8k8)
#define BM 128
#define BN 64
#define BK 16

// swizzled column for element (row, k) in a [row][16] tile:
// col' = (k + 4*((row>>1)&3)) & 15   -> conflict-free fragment LDS, float4 stores
__device__ __forceinline__ int swz(int k, int row) {
    return (k + (((row >> 1) & 3) << 2)) & 15;
}

__global__ void __launch_bounds__(256, 1)
gemm_epi(const float* __restrict__ x,
         const float* __restrict__ Wf, const float* __restrict__ bf,
         const float* __restrict__ Wi, const float* __restrict__ bi,
         const float* __restrict__ Wh, const float* __restrict__ bh,
         int M)
{
    __shared__ uint32_t xs[2][BM][16];       // 16 KB
    __shared__ uint32_t ws[2][3][BN][16];    // 24 KB

    const int tid  = threadIdx.x;
    const int lane = tid & 31;
    const int wid  = tid >> 5;
    const int g    = lane >> 2;   // groupID
    const int t    = lane & 3;    // threadID_in_group

    const int m0 = blockIdx.y * BM;
    const int n0 = blockIdx.x * BN;

    const int warpM = (wid >> 1) * 32;   // 0,32,64,96
    const int warpN = (wid & 1) * 32;    // 0,32

    // loader indices
    const int xr0 = tid >> 2;            // 0..63
    const int xr1 = (tid + 256) >> 2;    // 64..127
    const int xq  = tid & 3;             // k-quad
    const int wr  = tid >> 2;            // 0..63
    const int wq  = tid & 3;

    const float* Wg[3] = {Wf, Wi, Wh};

    float acc[3][2][4][4];
#pragma unroll
    for (int gt = 0; gt < 3; gt++)
#pragma unroll
        for (int mt = 0; mt < 2; mt++)
#pragma unroll
            for (int nt = 0; nt < 4; nt++)
#pragma unroll
                for (int c = 0; c < 4; c++) acc[gt][mt][nt][c] = 0.0f;

    const int NT = D_DIM / BK;   // 64

    float4 pxv0, pxv1, pwv0, pwv1, pwv2;

    // helper lambda-ish macros for swizzled float4->tf32 store
#define STORE_X(stage, row, q, v)                                           \
    {                                                                       \
        int c4 = ((q) + (((row) >> 1) & 3)) & 3;                            \
        uint32_t* d = &xs[stage][row][c4 * 4];                              \
        d[0] = f2tf32((v).x); d[1] = f2tf32((v).y);                         \
        d[2] = f2tf32((v).z); d[3] = f2tf32((v).w);                         \
    }
#define STORE_W(stage, gate, row, q, v)                                     \
    {                                                                       \
        int c4 = ((q) + (((row) >> 1) & 3)) & 3;                            \
        uint32_t* d = &ws[stage][gate][row][c4 * 4];                        \
        d[0] = f2tf32((v).x); d[1] = f2tf32((v).y);                         \
        d[2] = f2tf32((v).z); d[3] = f2tf32((v).w);                         \
    }

    // prologue: tile 0 -> stage 0
    {
        pxv0 = *(const float4*)&x[(size_t)(m0 + xr0) * D_DIM + xq * 4];
        pxv1 = *(const float4*)&x[(size_t)(m0 + xr1) * D_DIM + xq * 4];
        pwv0 = *(const float4*)&Wg[0][(size_t)(n0 + wr) * D_DIM + wq * 4];
        pwv1 = *(const float4*)&Wg[1][(size_t)(n0 + wr) * D_DIM + wq * 4];
        pwv2 = *(const float4*)&Wg[2][(size_t)(n0 + wr) * D_DIM + wq * 4];
        STORE_X(0, xr0, xq, pxv0);
        STORE_X(0, xr1, xq, pxv1);
        STORE_W(0, 0, wr, wq, pwv0);
        STORE_W(0, 1, wr, wq, pwv1);
        STORE_W(0, 2, wr, wq, pwv2);
    }
    __syncthreads();

    for (int kt = 0; kt < NT; kt++) {
        const int buf = kt & 1;
        const int nbuf = buf ^ 1;

        if (kt + 1 < NT) {
            const int k0 = (kt + 1) * BK;
            pxv0 = *(const float4*)&x[(size_t)(m0 + xr0) * D_DIM + k0 + xq * 4];
            pxv1 = *(const float4*)&x[(size_t)(m0 + xr1) * D_DIM + k0 + xq * 4];
            pwv0 = *(const float4*)&Wg[0][(size_t)(n0 + wr) * D_DIM + k0 + wq * 4];
            pwv1 = *(const float4*)&Wg[1][(size_t)(n0 + wr) * D_DIM + k0 + wq * 4];
            pwv2 = *(const float4*)&Wg[2][(size_t)(n0 + wr) * D_DIM + k0 + wq * 4];
        }

        // two k8 steps in this BK=16 tile
#pragma unroll
        for (int s = 0; s < 2; s++) {
            const int kb = s * 8;
            // A fragments (shared across the 3 gates)
            uint32_t a[2][4];
#pragma unroll
            for (int mt = 0; mt < 2; mt++) {
                const int r0 = warpM + mt * 16 + g;
                const int r1 = r0 + 8;
                a[mt][0] = xs[buf][r0][swz(kb + t,     r0)];
                a[mt][1] = xs[buf][r1][swz(kb + t,     r1)];
                a[mt][2] = xs[buf][r0][swz(kb + t + 4, r0)];
                a[mt][3] = xs[buf][r1][swz(kb + t + 4, r1)];
            }
#pragma unroll
            for (int gt = 0; gt < 3; gt++) {
                uint32_t b[4][2];
#pragma unroll
                for (int nt = 0; nt < 4; nt++) {
                    const int rB = warpN + nt * 8 + g;
                    b[nt][0] = ws[buf][gt][rB][swz(kb + t,     rB)];
                    b[nt][1] = ws[buf][gt][rB][swz(kb + t + 4, rB)];
                }
#pragma unroll
                for (int mt = 0; mt < 2; mt++)
#pragma unroll
                    for (int nt = 0; nt < 4; nt++) {
                        float* c = acc[gt][mt][nt];
                        asm volatile(
                            "mma.sync.aligned.m16n8k8.row.col.f32.tf32.tf32.f32 "
                            "{%0,%1,%2,%3}, {%4,%5,%6,%7}, {%8,%9}, {%0,%1,%2,%3};"
                            : "+f"(c[0]), "+f"(c[1]), "+f"(c[2]), "+f"(c[3])
                            : "r"(a[mt][0]), "r"(a[mt][1]), "r"(a[mt][2]), "r"(a[mt][3]),
                              "r"(b[nt][0]), "r"(b[nt][1]));
                    }
            }
        }

        if (kt + 1 < NT) {
            STORE_X(nbuf, xr0, xq, pxv0);
            STORE_X(nbuf, xr1, xq, pxv1);
            STORE_W(nbuf, 0, wr, wq, pwv0);
            STORE_W(nbuf, 1, wr, wq, pwv1);
            STORE_W(nbuf, 2, wr, wq, pwv2);
        }
        __syncthreads();
    }

    // ---- epilogue: bias + gate math -> g_logf / g_logv ----
    float bfv[4][2], biv[4][2], bhv[4][2];
#pragma unroll
    for (int nt = 0; nt < 4; nt++)
#pragma unroll
        for (int e = 0; e < 2; e++) {
            const int n = n0 + warpN + nt * 8 + 2 * t + e;
            bfv[nt][e] = bf[n];
            biv[nt][e] = bi[n];
            bhv[nt][e] = bh[n];
        }

#pragma unroll
    for (int mt = 0; mt < 2; mt++) {
#pragma unroll
        for (int hh = 0; hh < 2; hh++) {
            const int m = m0 + warpM + mt * 16 + hh * 8 + g;
            const size_t rowoff = (size_t)m * H_DIM + n0 + warpN;
#pragma unroll
            for (int nt = 0; nt < 4; nt++) {
#pragma unroll
                for (int e = 0; e < 2; e++) {
                    const int ci = hh * 2 + e;
                    float zf = acc[0][mt][nt][ci] + bfv[nt][e];
                    float zi = acc[1][mt][nt][ci] + biv[nt][e];
                    float zh = acc[2][mt][nt][ci] + bhv[nt][e];
                    float diff  = splus(-zf) - splus(-zi);
                    float logF  = -splus(diff);
                    float logI  = -splus(-diff);
                    float logGh = log_g(zh);
                    const size_t o = rowoff + nt * 8 + 2 * t + e;
                    g_logf[o] = logF;
                    g_logv[o] = logI + logGh;
                }
            }
        }
    }
}

// ---------------- pass 1: per-chunk composed operator ------------------------
__global__ void scan_chunks(int B)
{
    const size_t gid = (size_t)blockIdx.x * blockDim.x + threadIdx.x;
    const int h = (int)(gid % H_DIM);
    const size_t bc = gid / H_DIM;
    const int c = (int)(bc % CHUNKS);
    const int b = (int)(bc / CHUNKS);
    if (b >= B) return;

    size_t idx = ((size_t)b * T_DIM + (size_t)c * CLEN) * H_DIM + h;
    float A  = g_logf[idx];
    float Bv = g_logv[idx];
#pragma unroll 4
    for (int t = 1; t < CLEN; t++) {
        idx += H_DIM;
        float a  = g_logf[idx];
        float bb = g_logv[idx];
        A += a;
        Bv = lae(Bv + a, bb);
    }
    const size_t co = ((size_t)b * CHUNKS + c) * H_DIM + h;
    g_cA[co] = A;
    g_cB[co] = Bv;
}

// ---------------- pass 2: scan across chunks (per channel) -------------------
__global__ void scan_across(const float* __restrict__ h0, int B)
{
    const size_t gid = (size_t)blockIdx.x * blockDim.x + threadIdx.x;
    const int h = (int)(gid % H_DIM);
    const int b = (int)(gid / H_DIM);
    if (b >= B) return;

    float state = log_g(h0[(size_t)b * H_DIM + h]);
#pragma unroll
    for (int c = 0; c < CHUNKS; c++) {
        const size_t co = ((size_t)b * CHUNKS + c) * H_DIM + h;
        g_cS[co] = state;
        state = lae(state + g_cA[co], g_cB[co]);
    }
}

// ---------------- pass 3: final within-chunk scan + exp ----------------------
__global__ void scan_final(float* __restrict__ out, int B)
{
    const size_t gid = (size_t)blockIdx.x * blockDim.x + threadIdx.x;
    const int h = (int)(gid % H_DIM);
    const size_t bc = gid / H_DIM;
    const int c = (int)(bc % CHUNKS);
    const int b = (int)(bc / CHUNKS);
    if (b >= B) return;

    const size_t co = ((size_t)b * CHUNKS + c) * H_DIM + h;
    float state = g_cS[co];

    size_t idx = ((size_t)b * T_DIM + (size_t)c * CLEN) * H_DIM + h;
#pragma unroll 4
    for (int t = 0; t < CLEN; t++) {
        float a  = g_logf[idx];
        float bb = g_logv[idx];
        state = lae(state + a, bb);
        out[idx] = expf(state);
        idx += H_DIM;
    }
}

// ---------------- launch ------------------------------------------------------
extern "C" void kernel_launch(void* const* d_in, const int* in_sizes, int n_in,
                              void* d_out, int out_size)
{
    const float* x  = (const float*)d_in[0];
    const float* h0 = (const float*)d_in[1];
    const float* Wf = (const float*)d_in[2];
    const float* bf = (const float*)d_in[3];
    const float* Wi = (const float*)d_in[4];
    const float* bi = (const float*)d_in[5];
    const float* Wh = (const float*)d_in[6];
    const float* bh = (const float*)d_in[7];
    float* out = (float*)d_out;

    const int M = in_sizes[0] / D_DIM;   // B*T = 32768
    const int B = M / T_DIM;             // 8

    dim3 gGemm(H_DIM / BN, M / BM);      // (16, 256)
    gemm_epi<<<gGemm, 256>>>(x, Wf, bf, Wi, bi, Wh, bh, M);

    const int nChunkThreads = B * CHUNKS * H_DIM;     // 262144
    scan_chunks<<<nChunkThreads / 256, 256>>>(B);

    const int nChanThreads = B * H_DIM;               // 8192
    scan_across<<<nChanThreads / 256, 256>>>(h0, B);

    scan_final<<<nChunkThreads / 256, 256>>>(out, B);
}

// round 4
// speedup vs baseline: 3.8830x; 1.5845x over previous
#include <cuda_runtime.h>
#include <math.h>
#include <stdint.h>

#define T_DIM 4096
#define D_DIM 1024
#define H_DIM 1024
#define B_MAX 8

#define CHUNKS 32
#define CLEN   (T_DIM / CHUNKS)   // 128

// ---------------- scratch (device globals) -----------------------------------
__device__ float g_logf[(size_t)B_MAX * T_DIM * H_DIM];
__device__ float g_logv[(size_t)B_MAX * T_DIM * H_DIM];
__device__ float g_cA[(size_t)B_MAX * CHUNKS * H_DIM];
__device__ float g_cB[(size_t)B_MAX * CHUNKS * H_DIM];
__device__ float g_cS[(size_t)B_MAX * CHUNKS * H_DIM];

// ---------------- math helpers -------------------------------------------------
__device__ __forceinline__ float splus(float x) {
    return fmaxf(x, 0.0f) + log1pf(expf(-fabsf(x)));
}
__device__ __forceinline__ float lae(float a, float b) {
    float m = fmaxf(a, b);
    float d = fabsf(a - b);
    return m + log1pf(expf(-d));
}
__device__ __forceinline__ float log_g(float x) {
    return (x >= 0.0f) ? logf(x + 0.5f) : -splus(-x);
}
__device__ __forceinline__ uint32_t bf16x2(float lo, float hi) {
    uint32_t r;
    asm("cvt.rn.bf16x2.f32 %0, %1, %2;" : "=r"(r) : "f"(hi), "f"(lo));
    return r;
}

// ---------------- bf16 tensor-core fused 3-gate GEMM + epilogue ----------------
// z_g[m][h] = sum_d x[m][d] * W_g[h][d] + b_g[h]   (bf16 mma.m16n8k16, f32 acc)
#define BM 128
#define BN 64
#define BK 32          // 16 k-pairs per row

// swizzled k-pair column: conflict-free fragment LDS
__device__ __forceinline__ int swz(int kp, int row) {
    return (kp + 2 * (row & 7)) & 15;
}

__global__ void __launch_bounds__(256, 1)
gemm_epi(const float* __restrict__ x,
         const float* __restrict__ Wf, const float* __restrict__ bf,
         const float* __restrict__ Wi, const float* __restrict__ bi,
         const float* __restrict__ Wh, const float* __restrict__ bh,
         int M)
{
    __shared__ uint32_t xs[2][BM][16];       // 16 KB (bf16x2 words)
    __shared__ uint32_t ws[2][3][BN][16];    // 24 KB

    const int tid  = threadIdx.x;
    const int lane = tid & 31;
    const int wid  = tid >> 5;
    const int g    = lane >> 2;   // groupID
    const int t    = lane & 3;    // threadID_in_group

    const int m0 = blockIdx.y * BM;
    const int n0 = blockIdx.x * BN;

    const int warpM = (wid >> 1) * 32;   // 0,32,64,96
    const int warpN = (wid & 1) * 32;    // 0,32

    // loader indices: x tile = 1024 float4 (4/thread), W per gate = 512 (2/thread)
    int xrow[4], xq[4], wrow[2], wq[2];
#pragma unroll
    for (int i = 0; i < 4; i++) { int p = tid + 256 * i; xrow[i] = p >> 3; xq[i] = p & 7; }
#pragma unroll
    for (int i = 0; i < 2; i++) { int p = tid + 256 * i; wrow[i] = p >> 3; wq[i] = p & 7; }

    const float* Wg[3] = {Wf, Wi, Wh};

    float acc[3][2][4][4];
#pragma unroll
    for (int gt = 0; gt < 3; gt++)
#pragma unroll
        for (int mt = 0; mt < 2; mt++)
#pragma unroll
            for (int nt = 0; nt < 4; nt++)
#pragma unroll
                for (int c = 0; c < 4; c++) acc[gt][mt][nt][c] = 0.0f;

    const int NT = D_DIM / BK;   // 32

    float4 pxv[4], pwv[3][2];

#define STORE_X(stage, row, q, v)                                              \
    {                                                                          \
        uint32_t u0 = bf16x2((v).x, (v).y);                                    \
        uint32_t u1 = bf16x2((v).z, (v).w);                                    \
        xs[stage][row][swz(2 * (q),     row)] = u0;                            \
        xs[stage][row][swz(2 * (q) + 1, row)] = u1;                            \
    }
#define STORE_W(stage, gate, row, q, v)                                        \
    {                                                                          \
        uint32_t u0 = bf16x2((v).x, (v).y);                                    \
        uint32_t u1 = bf16x2((v).z, (v).w);                                    \
        ws[stage][gate][row][swz(2 * (q),     row)] = u0;                      \
        ws[stage][gate][row][swz(2 * (q) + 1, row)] = u1;                      \
    }

    // prologue: tile 0 -> stage 0
    {
#pragma unroll
        for (int i = 0; i < 4; i++)
            pxv[i] = *(const float4*)&x[(size_t)(m0 + xrow[i]) * D_DIM + xq[i] * 4];
#pragma unroll
        for (int gt = 0; gt < 3; gt++)
#pragma unroll
            for (int i = 0; i < 2; i++)
                pwv[gt][i] = *(const float4*)&Wg[gt][(size_t)(n0 + wrow[i]) * D_DIM + wq[i] * 4];
#pragma unroll
        for (int i = 0; i < 4; i++) STORE_X(0, xrow[i], xq[i], pxv[i]);
#pragma unroll
        for (int gt = 0; gt < 3; gt++)
#pragma unroll
            for (int i = 0; i < 2; i++) STORE_W(0, gt, wrow[i], wq[i], pwv[gt][i]);
    }
    __syncthreads();

    for (int kt = 0; kt < NT; kt++) {
        const int buf = kt & 1;
        const int nbuf = buf ^ 1;

        if (kt + 1 < NT) {
            const int k0 = (kt + 1) * BK;
#pragma unroll
            for (int i = 0; i < 4; i++)
                pxv[i] = *(const float4*)&x[(size_t)(m0 + xrow[i]) * D_DIM + k0 + xq[i] * 4];
#pragma unroll
            for (int gt = 0; gt < 3; gt++)
#pragma unroll
                for (int i = 0; i < 2; i++)
                    pwv[gt][i] = *(const float4*)&Wg[gt][(size_t)(n0 + wrow[i]) * D_DIM + k0 + wq[i] * 4];
        }

        // two m16n8k16 steps per BK=32 tile (k-pairs [0..7], [8..15])
#pragma unroll
        for (int s = 0; s < 2; s++) {
            const int kb = s * 8;
            uint32_t a[2][4];
#pragma unroll
            for (int mt = 0; mt < 2; mt++) {
                const int r0 = warpM + mt * 16 + g;
                const int r1 = r0 + 8;
                a[mt][0] = xs[buf][r0][swz(kb + t,     r0)];
                a[mt][1] = xs[buf][r1][swz(kb + t,     r1)];
                a[mt][2] = xs[buf][r0][swz(kb + t + 4, r0)];
                a[mt][3] = xs[buf][r1][swz(kb + t + 4, r1)];
            }
#pragma unroll
            for (int gt = 0; gt < 3; gt++) {
                uint32_t b[4][2];
#pragma unroll
                for (int nt = 0; nt < 4; nt++) {
                    const int rB = warpN + nt * 8 + g;
                    b[nt][0] = ws[buf][gt][rB][swz(kb + t,     rB)];
                    b[nt][1] = ws[buf][gt][rB][swz(kb + t + 4, rB)];
                }
#pragma unroll
                for (int mt = 0; mt < 2; mt++)
#pragma unroll
                    for (int nt = 0; nt < 4; nt++) {
                        float* c = acc[gt][mt][nt];
                        asm volatile(
                            "mma.sync.aligned.m16n8k16.row.col.f32.bf16.bf16.f32 "
                            "{%0,%1,%2,%3}, {%4,%5,%6,%7}, {%8,%9}, {%0,%1,%2,%3};"
                            : "+f"(c[0]), "+f"(c[1]), "+f"(c[2]), "+f"(c[3])
                            : "r"(a[mt][0]), "r"(a[mt][1]), "r"(a[mt][2]), "r"(a[mt][3]),
                              "r"(b[nt][0]), "r"(b[nt][1]));
                    }
            }
        }

        if (kt + 1 < NT) {
#pragma unroll
            for (int i = 0; i < 4; i++) STORE_X(nbuf, xrow[i], xq[i], pxv[i]);
#pragma unroll
            for (int gt = 0; gt < 3; gt++)
#pragma unroll
                for (int i = 0; i < 2; i++) STORE_W(nbuf, gt, wrow[i], wq[i], pwv[gt][i]);
        }
        __syncthreads();
    }

    // ---- epilogue: bias + gate math -> g_logf / g_logv ----
    float bfv[4][2], biv[4][2], bhv[4][2];
#pragma unroll
    for (int nt = 0; nt < 4; nt++)
#pragma unroll
        for (int e = 0; e < 2; e++) {
            const int n = n0 + warpN + nt * 8 + 2 * t + e;
            bfv[nt][e] = bf[n];
            biv[nt][e] = bi[n];
            bhv[nt][e] = bh[n];
        }

#pragma unroll
    for (int mt = 0; mt < 2; mt++) {
#pragma unroll
        for (int hh = 0; hh < 2; hh++) {
            const int m = m0 + warpM + mt * 16 + hh * 8 + g;
            const size_t rowoff = (size_t)m * H_DIM + n0 + warpN;
#pragma unroll
            for (int nt = 0; nt < 4; nt++) {
#pragma unroll
                for (int e = 0; e < 2; e++) {
                    const int ci = hh * 2 + e;
                    float zf = acc[0][mt][nt][ci] + bfv[nt][e];
                    float zi = acc[1][mt][nt][ci] + biv[nt][e];
                    float zh = acc[2][mt][nt][ci] + bhv[nt][e];
                    float diff  = splus(-zf) - splus(-zi);
                    float logF  = -splus(diff);
                    float logI  = -splus(-diff);
                    float logGh = log_g(zh);
                    const size_t o = rowoff + nt * 8 + 2 * t + e;
                    g_logf[o] = logF;
                    g_logv[o] = logI + logGh;
                }
            }
        }
    }
}

// ---------------- pass 1: per-chunk composed operator ------------------------
__global__ void scan_chunks(int B)
{
    const size_t gid = (size_t)blockIdx.x * blockDim.x + threadIdx.x;
    const int h = (int)(gid % H_DIM);
    const size_t bc = gid / H_DIM;
    const int c = (int)(bc % CHUNKS);
    const int b = (int)(bc / CHUNKS);
    if (b >= B) return;

    size_t idx = ((size_t)b * T_DIM + (size_t)c * CLEN) * H_DIM + h;
    float A  = g_logf[idx];
    float Bv = g_logv[idx];
#pragma unroll 4
    for (int t = 1; t < CLEN; t++) {
        idx += H_DIM;
        float a  = g_logf[idx];
        float bb = g_logv[idx];
        A += a;
        Bv = lae(Bv + a, bb);
    }
    const size_t co = ((size_t)b * CHUNKS + c) * H_DIM + h;
    g_cA[co] = A;
    g_cB[co] = Bv;
}

// ---------------- pass 2: scan across chunks ---------------------------------
__global__ void scan_across(const float* __restrict__ h0, int B)
{
    const size_t gid = (size_t)blockIdx.x * blockDim.x + threadIdx.x;
    const int h = (int)(gid % H_DIM);
    const int b = (int)(gid / H_DIM);
    if (b >= B) return;

    float state = log_g(h0[(size_t)b * H_DIM + h]);
#pragma unroll
    for (int c = 0; c < CHUNKS; c++) {
        const size_t co = ((size_t)b * CHUNKS + c) * H_DIM + h;
        g_cS[co] = state;
        state = lae(state + g_cA[co], g_cB[co]);
    }
}

// ---------------- pass 3: final within-chunk scan + exp ----------------------
__global__ void scan_final(float* __restrict__ out, int B)
{
    const size_t gid = (size_t)blockIdx.x * blockDim.x + threadIdx.x;
    const int h = (int)(gid % H_DIM);
    const size_t bc = gid / H_DIM;
    const int c = (int)(bc % CHUNKS);
    const int b = (int)(bc / CHUNKS);
    if (b >= B) return;

    const size_t co = ((size_t)b * CHUNKS + c) * H_DIM + h;
    float state = g_cS[co];

    size_t idx = ((size_t)b * T_DIM + (size_t)c * CLEN) * H_DIM + h;
#pragma unroll 4
    for (int t = 0; t < CLEN; t++) {
        float a  = g_logf[idx];
        float bb = g_logv[idx];
        state = lae(state + a, bb);
        out[idx] = expf(state);
        idx += H_DIM;
    }
}

// ---------------- launch --------------------------------------------------------
extern "C" void kernel_launch(void* const* d_in, const int* in_sizes, int n_in,
                              void* d_out, int out_size)
{
    const float* x  = (const float*)d_in[0];
    const float* h0 = (const float*)d_in[1];
    const float* Wf = (const float*)d_in[2];
    const float* bf = (const float*)d_in[3];
    const float* Wi = (const float*)d_in[4];
    const float* bi = (const float*)d_in[5];
    const float* Wh = (const float*)d_in[6];
    const float* bh = (const float*)d_in[7];
    float* out = (float*)d_out;

    const int M = in_sizes[0] / D_DIM;   // 32768
    const int B = M / T_DIM;             // 8

    dim3 gGemm(H_DIM / BN, M / BM);      // (16, 256)
    gemm_epi<<<gGemm, 256>>>(x, Wf, bf, Wi, bi, Wh, bh, M);

    const int nChunkThreads = B * CHUNKS * H_DIM;
    scan_chunks<<<nChunkThreads / 256, 256>>>(B);

    const int nChanThreads = B * H_DIM;
    scan_across<<<nChanThreads / 256, 256>>>(h0, B);

    scan_final<<<nChunkThreads / 256, 256>>>(out, B);
}

// round 5
// speedup vs baseline: 3.9071x; 1.0062x over previous
#include <cuda_runtime.h>
#include <math.h>
#include <stdint.h>

#define T_DIM 4096
#define D_DIM 1024
#define H_DIM 1024
#define B_MAX 8

#define CHUNKS 32
#define CLEN   (T_DIM / CHUNKS)   // 128

// ---------------- scratch (device globals) -----------------------------------
__device__ float g_logf[(size_t)B_MAX * T_DIM * H_DIM];
__device__ float g_logv[(size_t)B_MAX * T_DIM * H_DIM];
__device__ float g_cA[(size_t)B_MAX * CHUNKS * H_DIM];
__device__ float g_cB[(size_t)B_MAX * CHUNKS * H_DIM];
__device__ float g_cS[(size_t)B_MAX * CHUNKS * H_DIM];

// ---------------- math helpers -------------------------------------------------
__device__ __forceinline__ float splus(float x) {
    return fmaxf(x, 0.0f) + log1pf(expf(-fabsf(x)));
}
__device__ __forceinline__ float lae(float a, float b) {
    float m = fmaxf(a, b);
    float d = fabsf(a - b);
    return m + log1pf(expf(-d));
}
__device__ __forceinline__ float log_g(float x) {
    return (x >= 0.0f) ? logf(x + 0.5f) : -splus(-x);
}
__device__ __forceinline__ uint32_t bf16x2(float lo, float hi) {
    uint32_t r;
    asm("cvt.rn.bf16x2.f32 %0, %1, %2;" : "=r"(r) : "f"(hi), "f"(lo));
    return r;
}
__device__ __forceinline__ uint32_t smem_u32(const void* p) {
    uint32_t a;
    asm("{ .reg .u64 t; cvta.to.shared.u64 t, %1; cvt.u32.u64 %0, t; }" : "=r"(a) : "l"(p));
    return a;
}

// granule (row, kb) -> byte offset inside one operand tile (64B rows, rot-swizzle)
__device__ __forceinline__ uint32_t goff(int row, int kb) {
    return (uint32_t)(row * 64 + (((kb + (row >> 1)) & 3) << 4));
}

#define LDSM_X4(r0, r1, r2, r3, addr)                                        \
    asm volatile("ldmatrix.sync.aligned.m8n8.x4.shared.b16 {%0,%1,%2,%3}, [%4];" \
                 : "=r"(r0), "=r"(r1), "=r"(r2), "=r"(r3) : "r"(addr))

#define STS128(addr, u0, u1, u2, u3)                                         \
    asm volatile("st.shared.v4.b32 [%0], {%1,%2,%3,%4};"                      \
                 :: "r"(addr), "r"(u0), "r"(u1), "r"(u2), "r"(u3) : "memory")

// ---------------- bf16 tensor-core fused 3-gate GEMM + epilogue ----------------
#define BM 128
#define BN 64
#define BK 32
#define STAGE_SZ 20480u   // A 8KB @0, B[g] 4KB @ 8192 + g*4096

__global__ void __launch_bounds__(256, 1)
gemm_epi(const float* __restrict__ x,
         const float* __restrict__ Wf, const float* __restrict__ bf,
         const float* __restrict__ Wi, const float* __restrict__ bi,
         const float* __restrict__ Wh, const float* __restrict__ bh,
         int M)
{
    __shared__ __align__(128) uint8_t smem[2 * STAGE_SZ];   // 40 KB
    const uint32_t sbase = smem_u32(smem);

    const int tid  = threadIdx.x;
    const int lane = tid & 31;
    const int wid  = tid >> 5;
    const int g    = lane >> 2;   // groupID
    const int t    = lane & 3;    // threadID_in_group

    const int m0 = blockIdx.y * BM;
    const int n0 = blockIdx.x * BN;

    const int warpM = (wid >> 1) * 32;   // 0,32,64,96
    const int warpN = (wid & 1) * 32;    // 0,32

    // ---- ldmatrix per-lane base addresses (step s=0; s=1 is ^0x20) ----
    const int lrow = ((lane >> 3) & 1) * 8 + (lane & 7);  // row within 16-row tile
    const int lkb  = lane >> 4;                           // kb 0/1 for s=0
    uint32_t aAddr[2], bAddr[3][2];
#pragma unroll
    for (int mt = 0; mt < 2; mt++)
        aAddr[mt] = sbase + goff(warpM + mt * 16 + lrow, lkb);
#pragma unroll
    for (int gt = 0; gt < 3; gt++)
#pragma unroll
        for (int h = 0; h < 2; h++)
            bAddr[gt][h] = sbase + 8192 + gt * 4096 + goff(warpN + h * 16 + lrow, lkb);

    // ---- loader indices: pass p=0..4 (A0,A1 at p<2 folded; B gate p) ----
    // A: thread handles granule (m = p*64 + (tid>>2), kb = tid&3), p = 0,1
    // B: gate p granule (n = tid>>2, kb = tid&3)
    const int grow = tid >> 2;
    const int gkb  = tid & 3;
    const float* Wg[3] = {Wf, Wi, Wh};

    const float* pA[2];
    pA[0] = x + (size_t)(m0 + grow) * D_DIM + gkb * 8;
    pA[1] = x + (size_t)(m0 + 64 + grow) * D_DIM + gkb * 8;
    const float* pB[3];
#pragma unroll
    for (int gt = 0; gt < 3; gt++)
        pB[gt] = Wg[gt] + (size_t)(n0 + grow) * D_DIM + gkb * 8;

    uint32_t aSts[2], bSts[3];
    aSts[0] = sbase + goff(grow, gkb);
    aSts[1] = sbase + goff(64 + grow, gkb);
#pragma unroll
    for (int gt = 0; gt < 3; gt++)
        bSts[gt] = sbase + 8192 + gt * 4096 + goff(grow, gkb);

    float acc[3][2][4][4];
#pragma unroll
    for (int gt = 0; gt < 3; gt++)
#pragma unroll
        for (int mt = 0; mt < 2; mt++)
#pragma unroll
            for (int nt = 0; nt < 4; nt++)
#pragma unroll
                for (int c = 0; c < 4; c++) acc[gt][mt][nt][c] = 0.0f;

    const int NT = D_DIM / BK;   // 32

    float4 v0[5], v1[5];   // staging: 5 granule-pairs (A p0, A p1, B f, B i, B h)

#define DO_LDG(kt)                                                             \
    {                                                                          \
        const int kc = (kt) * BK;                                              \
        v0[0] = *(const float4*)(pA[0] + kc);                                  \
        v1[0] = *(const float4*)(pA[0] + kc + 4);                              \
        v0[1] = *(const float4*)(pA[1] + kc);                                  \
        v1[1] = *(const float4*)(pA[1] + kc + 4);                              \
        v0[2] = *(const float4*)(pB[0] + kc);                                  \
        v1[2] = *(const float4*)(pB[0] + kc + 4);                              \
        v0[3] = *(const float4*)(pB[1] + kc);                                  \
        v1[3] = *(const float4*)(pB[1] + kc + 4);                              \
        v0[4] = *(const float4*)(pB[2] + kc);                                  \
        v1[4] = *(const float4*)(pB[2] + kc + 4);                              \
    }
#define DO_STS(sel)                                                            \
    {                                                                          \
        uint32_t sts[5] = {aSts[0] + (sel), aSts[1] + (sel),                   \
                           bSts[0] + (sel), bSts[1] + (sel), bSts[2] + (sel)}; \
        _Pragma("unroll")                                                      \
        for (int p = 0; p < 5; p++) {                                          \
            uint32_t u0 = bf16x2(v0[p].x, v0[p].y);                            \
            uint32_t u1 = bf16x2(v0[p].z, v0[p].w);                            \
            uint32_t u2 = bf16x2(v1[p].x, v1[p].y);                            \
            uint32_t u3 = bf16x2(v1[p].z, v1[p].w);                            \
            STS128(sts[p], u0, u1, u2, u3);                                    \
        }                                                                      \
    }

    // prologue: tile 0 -> stage 0
    DO_LDG(0);
    DO_STS(0u);
    __syncthreads();

    for (int kt = 0; kt < NT; kt++) {
        const uint32_t sel  = (uint32_t)(kt & 1) * STAGE_SZ;
        const uint32_t nsel = sel ^ STAGE_SZ;

        if (kt + 1 < NT) DO_LDG(kt + 1);

#pragma unroll
        for (int s = 0; s < 2; s++) {
            const uint32_t sx = (uint32_t)(s << 5);
            uint32_t a[2][4];
#pragma unroll
            for (int mt = 0; mt < 2; mt++)
                LDSM_X4(a[mt][0], a[mt][1], a[mt][2], a[mt][3],
                        (aAddr[mt] ^ sx) + sel);
#pragma unroll
            for (int gt = 0; gt < 3; gt++) {
                uint32_t bb[2][4];
#pragma unroll
                for (int h = 0; h < 2; h++)
                    LDSM_X4(bb[h][0], bb[h][1], bb[h][2], bb[h][3],
                            (bAddr[gt][h] ^ sx) + sel);
#pragma unroll
                for (int mt = 0; mt < 2; mt++)
#pragma unroll
                    for (int nt = 0; nt < 4; nt++) {
                        float* c = acc[gt][mt][nt];
                        const uint32_t b0 = bb[nt >> 1][nt & 1];
                        const uint32_t b1 = bb[nt >> 1][(nt & 1) + 2];
                        asm volatile(
                            "mma.sync.aligned.m16n8k16.row.col.f32.bf16.bf16.f32 "
                            "{%0,%1,%2,%3}, {%4,%5,%6,%7}, {%8,%9}, {%0,%1,%2,%3};"
                            : "+f"(c[0]), "+f"(c[1]), "+f"(c[2]), "+f"(c[3])
                            : "r"(a[mt][0]), "r"(a[mt][1]), "r"(a[mt][2]), "r"(a[mt][3]),
                              "r"(b0), "r"(b1));
                    }
            }
        }

        if (kt + 1 < NT) DO_STS(nsel);
        __syncthreads();
    }

    // ---- epilogue: bias + gate math -> g_logf / g_logv ----
    float bfv[4][2], biv[4][2], bhv[4][2];
#pragma unroll
    for (int nt = 0; nt < 4; nt++)
#pragma unroll
        for (int e = 0; e < 2; e++) {
            const int n = n0 + warpN + nt * 8 + 2 * t + e;
            bfv[nt][e] = bf[n];
            biv[nt][e] = bi[n];
            bhv[nt][e] = bh[n];
        }

#pragma unroll
    for (int mt = 0; mt < 2; mt++) {
#pragma unroll
        for (int hh = 0; hh < 2; hh++) {
            const int m = m0 + warpM + mt * 16 + hh * 8 + g;
            const size_t rowoff = (size_t)m * H_DIM + n0 + warpN;
#pragma unroll
            for (int nt = 0; nt < 4; nt++) {
#pragma unroll
                for (int e = 0; e < 2; e++) {
                    const int ci = hh * 2 + e;
                    float zf = acc[0][mt][nt][ci] + bfv[nt][e];
                    float zi = acc[1][mt][nt][ci] + biv[nt][e];
                    float zh = acc[2][mt][nt][ci] + bhv[nt][e];
                    float diff  = splus(-zf) - splus(-zi);
                    float logF  = -splus(diff);
                    float logI  = -splus(-diff);
                    float logGh = log_g(zh);
                    const size_t o = rowoff + nt * 8 + 2 * t + e;
                    g_logf[o] = logF;
                    g_logv[o] = logI + logGh;
                }
            }
        }
    }
}

// ---------------- pass 1: per-chunk composed operator ------------------------
__global__ void scan_chunks(int B)
{
    const size_t gid = (size_t)blockIdx.x * blockDim.x + threadIdx.x;
    const int h = (int)(gid % H_DIM);
    const size_t bc = gid / H_DIM;
    const int c = (int)(bc % CHUNKS);
    const int b = (int)(bc / CHUNKS);
    if (b >= B) return;

    size_t idx = ((size_t)b * T_DIM + (size_t)c * CLEN) * H_DIM + h;
    float A  = g_logf[idx];
    float Bv = g_logv[idx];
#pragma unroll 4
    for (int t = 1; t < CLEN; t++) {
        idx += H_DIM;
        float a  = g_logf[idx];
        float bb = g_logv[idx];
        A += a;
        Bv = lae(Bv + a, bb);
    }
    const size_t co = ((size_t)b * CHUNKS + c) * H_DIM + h;
    g_cA[co] = A;
    g_cB[co] = Bv;
}

// ---------------- pass 2: scan across chunks ---------------------------------
__global__ void scan_across(const float* __restrict__ h0, int B)
{
    const size_t gid = (size_t)blockIdx.x * blockDim.x + threadIdx.x;
    const int h = (int)(gid % H_DIM);
    const int b = (int)(gid / H_DIM);
    if (b >= B) return;

    float state = log_g(h0[(size_t)b * H_DIM + h]);
#pragma unroll
    for (int c = 0; c < CHUNKS; c++) {
        const size_t co = ((size_t)b * CHUNKS + c) * H_DIM + h;
        g_cS[co] = state;
        state = lae(state + g_cA[co], g_cB[co]);
    }
}

// ---------------- pass 3: final within-chunk scan + exp ----------------------
__global__ void scan_final(float* __restrict__ out, int B)
{
    const size_t gid = (size_t)blockIdx.x * blockDim.x + threadIdx.x;
    const int h = (int)(gid % H_DIM);
    const size_t bc = gid / H_DIM;
    const int c = (int)(bc % CHUNKS);
    const int b = (int)(bc / CHUNKS);
    if (b >= B) return;

    const size_t co = ((size_t)b * CHUNKS + c) * H_DIM + h;
    float state = g_cS[co];

    size_t idx = ((size_t)b * T_DIM + (size_t)c * CLEN) * H_DIM + h;
#pragma unroll 4
    for (int t = 0; t < CLEN; t++) {
        float a  = g_logf[idx];
        float bb = g_logv[idx];
        state = lae(state + a, bb);
        out[idx] = expf(state);
        idx += H_DIM;
    }
}

// ---------------- launch --------------------------------------------------------
extern "C" void kernel_launch(void* const* d_in, const int* in_sizes, int n_in,
                              void* d_out, int out_size)
{
    const float* x  = (const float*)d_in[0];
    const float* h0 = (const float*)d_in[1];
    const float* Wf = (const float*)d_in[2];
    const float* bf = (const float*)d_in[3];
    const float* Wi = (const float*)d_in[4];
    const float* bi = (const float*)d_in[5];
    const float* Wh = (const float*)d_in[6];
    const float* bh = (const float*)d_in[7];
    float* out = (float*)d_out;

    const int M = in_sizes[0] / D_DIM;   // 32768
    const int B = M / T_DIM;             // 8

    dim3 gGemm(H_DIM / BN, M / BM);      // (16, 256)
    gemm_epi<<<gGemm, 256>>>(x, Wf, bf, Wi, bi, Wh, bh, M);

    const int nChunkThreads = B * CHUNKS * H_DIM;
    scan_chunks<<<nChunkThreads / 256, 256>>>(B);

    const int nChanThreads = B * H_DIM;
    scan_across<<<nChanThreads / 256, 256>>>(h0, B);

    scan_final<<<nChunkThreads / 256, 256>>>(out, B);
}

// round 6
// speedup vs baseline: 4.5961x; 1.1764x over previous
#include <cuda_runtime.h>
#include <cuda_bf16.h>
#include <math.h>
#include <stdint.h>

#define T_DIM 4096
#define D_DIM 1024
#define H_DIM 1024
#define B_MAX 8

#define CHUNKS 32
#define CLEN   (T_DIM / CHUNKS)   // 128

// ---------------- scratch (device globals) -----------------------------------
__device__ float g_logf[(size_t)B_MAX * T_DIM * H_DIM];
__device__ float g_logv[(size_t)B_MAX * T_DIM * H_DIM];
__device__ float g_cA[(size_t)B_MAX * CHUNKS * H_DIM];
__device__ float g_cB[(size_t)B_MAX * CHUNKS * H_DIM];
__device__ float g_cS[(size_t)B_MAX * CHUNKS * H_DIM];
__device__ __align__(16) __nv_bfloat16 g_xbf[(size_t)B_MAX * T_DIM * D_DIM]; // 64MB
__device__ __align__(16) __nv_bfloat16 g_wbf[3][(size_t)H_DIM * D_DIM];      // 6MB

// ---------------- math helpers -------------------------------------------------
__device__ __forceinline__ float splus(float x) {
    return fmaxf(x, 0.0f) + log1pf(expf(-fabsf(x)));
}
__device__ __forceinline__ float lae(float a, float b) {
    float m = fmaxf(a, b);
    float d = fabsf(a - b);
    return m + log1pf(expf(-d));
}
__device__ __forceinline__ float log_g(float x) {
    return (x >= 0.0f) ? logf(x + 0.5f) : -splus(-x);
}
__device__ __forceinline__ uint32_t bf16x2(float lo, float hi) {
    uint32_t r;
    asm("cvt.rn.bf16x2.f32 %0, %1, %2;" : "=r"(r) : "f"(hi), "f"(lo));
    return r;
}
__device__ __forceinline__ uint32_t smem_u32(const void* p) {
    uint32_t a;
    asm("{ .reg .u64 t; cvta.to.shared.u64 t, %1; cvt.u32.u64 %0, t; }" : "=r"(a) : "l"(p));
    return a;
}

// granule (row, kb) -> byte offset inside one operand tile (64B rows, rot-swizzle)
__device__ __forceinline__ uint32_t goff(int row, int kb) {
    return (uint32_t)(row * 64 + (((kb + (row >> 1)) & 3) << 4));
}

#define LDSM_X4(r0, r1, r2, r3, addr)                                            \
    asm volatile("ldmatrix.sync.aligned.m8n8.x4.shared.b16 {%0,%1,%2,%3}, [%4];" \
                 : "=r"(r0), "=r"(r1), "=r"(r2), "=r"(r3) : "r"(addr))

#define CP16(dst, src)                                                           \
    asm volatile("cp.async.cg.shared.global [%0], [%1], 16;"                     \
                 :: "r"(dst), "l"(src) : "memory")

// ---------------- convert fp32 -> bf16 (8 elems/thread) ------------------------
__global__ void __launch_bounds__(256)
to_bf16(const float* __restrict__ src, __nv_bfloat16* __restrict__ dst)
{
    const size_t i = ((size_t)blockIdx.x * blockDim.x + threadIdx.x) * 8;
    float4 a = *(const float4*)(src + i);
    float4 b = *(const float4*)(src + i + 4);
    uint4 o;
    o.x = bf16x2(a.x, a.y);
    o.y = bf16x2(a.z, a.w);
    o.z = bf16x2(b.x, b.y);
    o.w = bf16x2(b.z, b.w);
    *(uint4*)(dst + i) = o;
}

// ---------------- bf16 tensor-core fused 3-gate GEMM + epilogue ----------------
#define BM 128
#define BN 64
#define BK 32
#define STAGES 4
#define STAGE_SZ 20480u   // A 8KB @0, B[g] 4KB @ 8192 + g*4096
#define GEMM_SMEM (STAGES * STAGE_SZ)   // 80KB

__global__ void __launch_bounds__(256, 1)
gemm_epi(const float* __restrict__ bf,
         const float* __restrict__ bi,
         const float* __restrict__ bh)
{
    extern __shared__ __align__(128) uint8_t smem[];
    const uint32_t sbase = smem_u32(smem);

    const int tid  = threadIdx.x;
    const int lane = tid & 31;
    const int wid  = tid >> 5;
    const int g    = lane >> 2;
    const int t    = lane & 3;

    const int m0 = blockIdx.y * BM;
    const int n0 = blockIdx.x * BN;

    const int warpM = (wid >> 1) * 32;
    const int warpN = (wid & 1) * 32;

    // ---- ldmatrix per-lane base addresses (step s=0; s=1 is ^0x20) ----
    const int lrow = ((lane >> 3) & 1) * 8 + (lane & 7);
    const int lkb  = lane >> 4;
    uint32_t aAddr[2], bAddr[3][2];
#pragma unroll
    for (int mt = 0; mt < 2; mt++)
        aAddr[mt] = sbase + goff(warpM + mt * 16 + lrow, lkb);
#pragma unroll
    for (int gt = 0; gt < 3; gt++)
#pragma unroll
        for (int h = 0; h < 2; h++)
            bAddr[gt][h] = sbase + 8192 + gt * 4096 + goff(warpN + h * 16 + lrow, lkb);

    // ---- cp.async loader: 5 granules (16B) per thread per stage ----
    const int grow = tid >> 2;   // 0..63
    const int gkb  = tid & 3;

    const __nv_bfloat16* srcA0 = g_xbf + (size_t)(m0 + grow) * D_DIM + gkb * 8;
    const __nv_bfloat16* srcA1 = g_xbf + (size_t)(m0 + 64 + grow) * D_DIM + gkb * 8;
    const __nv_bfloat16* srcB[3];
#pragma unroll
    for (int gt = 0; gt < 3; gt++)
        srcB[gt] = g_wbf[gt] + (size_t)(n0 + grow) * D_DIM + gkb * 8;

    const uint32_t dA0 = sbase + goff(grow, gkb);
    const uint32_t dA1 = sbase + goff(64 + grow, gkb);
    uint32_t dB[3];
#pragma unroll
    for (int gt = 0; gt < 3; gt++)
        dB[gt] = sbase + 8192 + gt * 4096 + goff(grow, gkb);

    float acc[3][2][4][4];
#pragma unroll
    for (int gt = 0; gt < 3; gt++)
#pragma unroll
        for (int mt = 0; mt < 2; mt++)
#pragma unroll
            for (int nt = 0; nt < 4; nt++)
#pragma unroll
                for (int c = 0; c < 4; c++) acc[gt][mt][nt][c] = 0.0f;

    const int NT = D_DIM / BK;   // 32

#define LOAD_STAGE(st, kt)                                                     \
    {                                                                          \
        const uint32_t so = (uint32_t)(st) * STAGE_SZ;                         \
        const int ko = (kt) * BK;                                              \
        CP16(dA0 + so,   srcA0 + ko);                                          \
        CP16(dA1 + so,   srcA1 + ko);                                          \
        CP16(dB[0] + so, srcB[0] + ko);                                        \
        CP16(dB[1] + so, srcB[1] + ko);                                        \
        CP16(dB[2] + so, srcB[2] + ko);                                        \
    }

    // prologue: fill STAGES-1 stages
#pragma unroll
    for (int s = 0; s < STAGES - 1; s++) {
        LOAD_STAGE(s, s);
        asm volatile("cp.async.commit_group;" ::: "memory");
    }

    for (int kt = 0; kt < NT; kt++) {
        const uint32_t sel = (uint32_t)(kt % STAGES) * STAGE_SZ;

        asm volatile("cp.async.wait_group %0;" :: "n"(STAGES - 2) : "memory");
        __syncthreads();

#pragma unroll
        for (int s = 0; s < 2; s++) {
            const uint32_t sx = (uint32_t)(s << 5);
            uint32_t a[2][4];
#pragma unroll
            for (int mt = 0; mt < 2; mt++)
                LDSM_X4(a[mt][0], a[mt][1], a[mt][2], a[mt][3],
                        (aAddr[mt] ^ sx) + sel);
#pragma unroll
            for (int gt = 0; gt < 3; gt++) {
                uint32_t bb[2][4];
#pragma unroll
                for (int h = 0; h < 2; h++)
                    LDSM_X4(bb[h][0], bb[h][1], bb[h][2], bb[h][3],
                            (bAddr[gt][h] ^ sx) + sel);
#pragma unroll
                for (int mt = 0; mt < 2; mt++)
#pragma unroll
                    for (int nt = 0; nt < 4; nt++) {
                        float* c = acc[gt][mt][nt];
                        const uint32_t b0 = bb[nt >> 1][nt & 1];
                        const uint32_t b1 = bb[nt >> 1][(nt & 1) + 2];
                        asm volatile(
                            "mma.sync.aligned.m16n8k16.row.col.f32.bf16.bf16.f32 "
                            "{%0,%1,%2,%3}, {%4,%5,%6,%7}, {%8,%9}, {%0,%1,%2,%3};"
                            : "+f"(c[0]), "+f"(c[1]), "+f"(c[2]), "+f"(c[3])
                            : "r"(a[mt][0]), "r"(a[mt][1]), "r"(a[mt][2]), "r"(a[mt][3]),
                              "r"(b0), "r"(b1));
                    }
            }
        }

        // issue next load (or empty group to keep wait_group bookkeeping exact)
        if (kt + STAGES - 1 < NT)
            LOAD_STAGE((kt + STAGES - 1) % STAGES, kt + STAGES - 1);
        asm volatile("cp.async.commit_group;" ::: "memory");
    }

    // ---- epilogue: bias + gate math -> g_logf / g_logv ----
    float bfv[4][2], biv[4][2], bhv[4][2];
#pragma unroll
    for (int nt = 0; nt < 4; nt++)
#pragma unroll
        for (int e = 0; e < 2; e++) {
            const int n = n0 + warpN + nt * 8 + 2 * t + e;
            bfv[nt][e] = bf[n];
            biv[nt][e] = bi[n];
            bhv[nt][e] = bh[n];
        }

#pragma unroll
    for (int mt = 0; mt < 2; mt++) {
#pragma unroll
        for (int hh = 0; hh < 2; hh++) {
            const int m = m0 + warpM + mt * 16 + hh * 8 + g;
            const size_t rowoff = (size_t)m * H_DIM + n0 + warpN;
#pragma unroll
            for (int nt = 0; nt < 4; nt++) {
#pragma unroll
                for (int e = 0; e < 2; e++) {
                    const int ci = hh * 2 + e;
                    float zf = acc[0][mt][nt][ci] + bfv[nt][e];
                    float zi = acc[1][mt][nt][ci] + biv[nt][e];
                    float zh = acc[2][mt][nt][ci] + bhv[nt][e];
                    float diff  = splus(-zf) - splus(-zi);
                    float logF  = -splus(diff);
                    float logI  = -splus(-diff);
                    float logGh = log_g(zh);
                    const size_t o = rowoff + nt * 8 + 2 * t + e;
                    g_logf[o] = logF;
                    g_logv[o] = logI + logGh;
                }
            }
        }
    }
}

// ---------------- pass 1: per-chunk composed operator ------------------------
__global__ void scan_chunks(int B)
{
    const size_t gid = (size_t)blockIdx.x * blockDim.x + threadIdx.x;
    const int h = (int)(gid % H_DIM);
    const size_t bc = gid / H_DIM;
    const int c = (int)(bc % CHUNKS);
    const int b = (int)(bc / CHUNKS);
    if (b >= B) return;

    size_t idx = ((size_t)b * T_DIM + (size_t)c * CLEN) * H_DIM + h;
    float A  = g_logf[idx];
    float Bv = g_logv[idx];
#pragma unroll 4
    for (int t = 1; t < CLEN; t++) {
        idx += H_DIM;
        float a  = g_logf[idx];
        float bb = g_logv[idx];
        A += a;
        Bv = lae(Bv + a, bb);
    }
    const size_t co = ((size_t)b * CHUNKS + c) * H_DIM + h;
    g_cA[co] = A;
    g_cB[co] = Bv;
}

// ---------------- pass 2: scan across chunks ---------------------------------
__global__ void scan_across(const float* __restrict__ h0, int B)
{
    const size_t gid = (size_t)blockIdx.x * blockDim.x + threadIdx.x;
    const int h = (int)(gid % H_DIM);
    const int b = (int)(gid / H_DIM);
    if (b >= B) return;

    float state = log_g(h0[(size_t)b * H_DIM + h]);
#pragma unroll
    for (int c = 0; c < CHUNKS; c++) {
        const size_t co = ((size_t)b * CHUNKS + c) * H_DIM + h;
        g_cS[co] = state;
        state = lae(state + g_cA[co], g_cB[co]);
    }
}

// ---------------- pass 3: final within-chunk scan + exp ----------------------
__global__ void scan_final(float* __restrict__ out, int B)
{
    const size_t gid = (size_t)blockIdx.x * blockDim.x + threadIdx.x;
    const int h = (int)(gid % H_DIM);
    const size_t bc = gid / H_DIM;
    const int c = (int)(bc % CHUNKS);
    const int b = (int)(bc / CHUNKS);
    if (b >= B) return;

    const size_t co = ((size_t)b * CHUNKS + c) * H_DIM + h;
    float state = g_cS[co];

    size_t idx = ((size_t)b * T_DIM + (size_t)c * CLEN) * H_DIM + h;
#pragma unroll 4
    for (int t = 0; t < CLEN; t++) {
        float a  = g_logf[idx];
        float bb = g_logv[idx];
        state = lae(state + a, bb);
        out[idx] = expf(state);
        idx += H_DIM;
    }
}

// ---------------- launch --------------------------------------------------------
extern "C" void kernel_launch(void* const* d_in, const int* in_sizes, int n_in,
                              void* d_out, int out_size)
{
    const float* x  = (const float*)d_in[0];
    const float* h0 = (const float*)d_in[1];
    const float* Wf = (const float*)d_in[2];
    const float* bf = (const float*)d_in[3];
    const float* Wi = (const float*)d_in[4];
    const float* bi = (const float*)d_in[5];
    const float* Wh = (const float*)d_in[6];
    const float* bh = (const float*)d_in[7];
    float* out = (float*)d_out;

    const int M = in_sizes[0] / D_DIM;   // 32768
    const int B = M / T_DIM;             // 8

    cudaFuncSetAttribute(gemm_epi, cudaFuncAttributeMaxDynamicSharedMemorySize,
                         GEMM_SMEM);

    // resolve device-global scratch addresses
    __nv_bfloat16* xbf;  cudaGetSymbolAddress((void**)&xbf, g_xbf);
    __nv_bfloat16* wbf;  cudaGetSymbolAddress((void**)&wbf, g_wbf);

    const size_t nx = (size_t)M * D_DIM;        // 33.55M
    to_bf16<<<(int)(nx / (8 * 256)), 256>>>(x, xbf);
    const size_t nw = (size_t)H_DIM * D_DIM;    // 1.05M each
    to_bf16<<<(int)(nw / (8 * 256)), 256>>>(Wf, wbf);
    to_bf16<<<(int)(nw / (8 * 256)), 256>>>(Wi, wbf + nw);
    to_bf16<<<(int)(nw / (8 * 256)), 256>>>(Wh, wbf + 2 * nw);

    dim3 gGemm(H_DIM / BN, M / BM);      // (16, 256)
    gemm_epi<<<gGemm, 256, GEMM_SMEM>>>(bf, bi, bh);

    const int nChunkThreads = B * CHUNKS * H_DIM;
    scan_chunks<<<nChunkThreads / 256, 256>>>(B);

    const int nChanThreads = B * H_DIM;
    scan_across<<<nChanThreads / 256, 256>>>(h0, B);

    scan_final<<<nChunkThreads / 256, 256>>>(out, B);
}